// round 15
// baseline (speedup 1.0000x reference)
#include <cuda_runtime.h>
#include <cuda_fp16.h>

#define NE 8
#define TT 8192
#define HH 1024
#define II 4096

typedef unsigned int u32;

// ---- pure fp16 operand planes ----
__device__ __half g_xh[(size_t)TT * HH];
__device__ __half g_w1h[(size_t)NE * HH * II];
__device__ __half g_w2h[(size_t)NE * II * HH];
__device__ __half g_uph[(size_t)TT * II];

// ---- smem stage (halves): A [128][40], B [32][72], BK = 32 ----
#define A_ROW 40
#define B_ROW 72
#define OFF_BH  (128 * A_ROW)                  // 5120
#define STAGE_H (OFF_BH + 32 * B_ROW)          // 7424 halves
#define STAGE_B (STAGE_H * 2)                  // 14848 bytes
#define NSTAGE  4
#define SMEM_BYTES (NSTAGE * STAGE_B)          // 59392 (x3 CTAs = 178KB/SM)

#define NSM 148

static __device__ __forceinline__ u32 smem_u32(const void* p) {
    u32 a;
    asm("{ .reg .u64 t; cvta.to.shared.u64 t, %1; cvt.u32.u64 %0, t; }" : "=r"(a) : "l"(p));
    return a;
}

#define CP16(dst, src) \
    asm volatile("cp.async.cg.shared.global [%0], [%1], 16;" :: "r"(dst), "l"(src))
#define CP_COMMIT() asm volatile("cp.async.commit_group;" ::: "memory")
#define CP_WAIT2()  asm volatile("cp.async.wait_group 2;" ::: "memory")

#define LDSM4(r, addr)                                                        \
    asm volatile("ldmatrix.sync.aligned.m8n8.x4.shared.b16 {%0,%1,%2,%3}, [%4];" \
                 : "=r"((r)[0]), "=r"((r)[1]), "=r"((r)[2]), "=r"((r)[3])     \
                 : "r"(addr))

#define LDSM4T(r, addr)                                                       \
    asm volatile("ldmatrix.sync.aligned.m8n8.x4.trans.shared.b16 {%0,%1,%2,%3}, [%4];" \
                 : "=r"((r)[0]), "=r"((r)[1]), "=r"((r)[2]), "=r"((r)[3])     \
                 : "r"(addr))

#define MMA16816(d, a, b0, b1)                                                \
    asm volatile("mma.sync.aligned.m16n8k16.row.col.f32.f16.f16.f32 "         \
                 "{%0,%1,%2,%3},{%4,%5,%6,%7},{%8,%9},{%0,%1,%2,%3};"         \
                 : "+f"((d)[0]), "+f"((d)[1]), "+f"((d)[2]), "+f"((d)[3])     \
                 : "r"((a)[0]), "r"((a)[1]), "r"((a)[2]), "r"((a)[3]),        \
                   "r"(b0), "r"(b1))

// fp32 -> fp16 plane
__global__ __launch_bounds__(256)
void cvt_hi_k(const float4* __restrict__ src, uint2* __restrict__ h, int n4)
{
    int i = blockIdx.x * 256 + threadIdx.x;
    if (i < n4) {
        float4 v = src[i];
        __half2 h0 = __float22half2_rn(make_float2(v.x, v.y));
        __half2 h1 = __float22half2_rn(make_float2(v.z, v.w));
        h[i] = make_uint2(*(u32*)&h0, *(u32*)&h1);
    }
}

// Persistent grouped GEMM: tiles 128(m) x 64(n), tile t -> n=(t%NTN), m=(t/NTN).
// A fp16 [T,K]; W fp16 [E,K,N]; EPI=0: fp32 C, EPI=1: fp16 Ch.
template <int K, int N, int EPI>
__global__ __launch_bounds__(128, 3)
void gemm_moe(const __half* __restrict__ Ah, const __half* __restrict__ Wh,
              const int* __restrict__ bsz, float* __restrict__ C,
              __half* __restrict__ Ch, int ntiles)
{
    constexpr int NTN = N / 64;
    extern __shared__ __half sm[];
    const u32 sbase = smem_u32(sm);
    const int tid = threadIdx.x;
    const int lane = tid & 31;
    const int wid = tid >> 5;
    const int warp_m = wid & 1;    // 2 warps along m (64 rows each)
    const int warp_n = wid >> 1;   // 2 warps along n (32 cols each)

    // ---- tile-invariant lane bases ----
    const int ar = tid >> 2, ac = tid & 3;   // A cp.async: rows ar+{0,32,64,96}
    const int bk = tid >> 3, bc = tid & 7;   // B cp.async: rows bk, bk+16
    const u32 dA = sbase + (u32)((ar * A_ROW + ac * 8) * 2);
    const u32 dB = sbase + (u32)(OFF_BH * 2 + (bk * B_ROW + bc * 8) * 2);
    const int a_r = lane & 15, a_c = (lane >> 4) * 8;
    const u32 aoff = sbase + (u32)(((warp_m * 64 + a_r) * A_ROW + a_c) * 2);
    const int b_k = (lane & 7) + 8 * ((lane >> 3) & 1);
    const int b_n = 8 * (lane >> 4);
    const u32 boff = sbase + (u32)((OFF_BH + b_k * B_ROW + warp_n * 32 + b_n) * 2);

    const int NS = K >> 5;

    for (int t = blockIdx.x; t < ntiles; t += gridDim.x) {
        const int n0 = (t % NTN) * 64;
        const int row0 = (t / NTN) * 128;

        int cum = 0, e = 0;
#pragma unroll
        for (int i = 0; i < NE; i++) { if (row0 >= cum) e = i; cum += bsz[i]; }
        const __half* pAh = Ah + (size_t)(row0 + ar) * K + ac * 8;
        const __half* pBh = Wh + (size_t)e * (size_t)K * N
                               + (size_t)bk * N + n0 + bc * 8;

        float acc[4][4][4];
#pragma unroll
        for (int mf = 0; mf < 4; mf++)
#pragma unroll
            for (int nf = 0; nf < 4; nf++)
#pragma unroll
                for (int v = 0; v < 4; v++) acc[mf][nf][v] = 0.0f;

        u32 fA[2][16], fB[2][8];

#define LOAD_STAGE(stoff)                                                     \
        do {                                                                  \
            const u32 _a = dA + (stoff);                                      \
            const u32 _b = dB + (stoff);                                      \
            CP16(_a,                       pAh);                              \
            CP16(_a + 32 * A_ROW * 2,      pAh + (size_t)32 * K);             \
            CP16(_a + 64 * A_ROW * 2,      pAh + (size_t)64 * K);             \
            CP16(_a + 96 * A_ROW * 2,      pAh + (size_t)96 * K);             \
            CP16(_b,                       pBh);                              \
            CP16(_b + 16 * B_ROW * 2,      pBh + (size_t)16 * N);             \
            pAh += 32;                                                        \
            pBh += (size_t)32 * N;                                            \
        } while (0)

#define LDSM_FRAGS(b, stoff, ki)                                              \
        do {                                                                  \
            const u32 _ka = aoff + (stoff) + (ki) * 32;                       \
            const u32 _kb = boff + (stoff) + (ki) * (16 * B_ROW * 2);         \
            LDSM4(&fA[b][0],  _ka);                                           \
            LDSM4(&fA[b][4],  _ka + 16 * A_ROW * 2);                          \
            LDSM4(&fA[b][8],  _ka + 32 * A_ROW * 2);                          \
            LDSM4(&fA[b][12], _ka + 48 * A_ROW * 2);                          \
            LDSM4T(&fB[b][0], _kb);                                           \
            LDSM4T(&fB[b][4], _kb + 16 * 2);                                  \
        } while (0)

#define BURST(b)                                                              \
        do {                                                                  \
            _Pragma("unroll")                                                 \
            for (int mf = 0; mf < 4; mf++)                                    \
                _Pragma("unroll")                                             \
                for (int nf = 0; nf < 4; nf++)                                \
                    MMA16816(acc[mf][nf], &fA[b][mf * 4], fB[b][nf * 2],      \
                             fB[b][nf * 2 + 1]);                              \
        } while (0)

        // protect smem reuse: all warps must be done reading the previous tile
        __syncthreads();

        // prologue: stages 0..2
        LOAD_STAGE(0);             CP_COMMIT();
        LOAD_STAGE(STAGE_B);       CP_COMMIT();
        LOAD_STAGE(2 * STAGE_B);   CP_COMMIT();

        int sidx = 0;
        for (int s = 0; s < NS; s++) {
            CP_WAIT2();
            __syncthreads();

            if (s + 3 < NS) {
                LOAD_STAGE((u32)(((sidx + 3) & 3) * STAGE_B));
            }
            CP_COMMIT();

            const u32 stb = (u32)(sidx * STAGE_B);
            sidx = (sidx + 1) & 3;

            LDSM_FRAGS(0, stb, 0);
            LDSM_FRAGS(1, stb, 1);
            BURST(0);
            BURST(1);
        }
#undef LOAD_STAGE
#undef LDSM_FRAGS
#undef BURST

        // ---- epilogue ----
#pragma unroll
        for (int mf = 0; mf < 4; mf++)
#pragma unroll
            for (int nf = 0; nf < 4; nf++) {
                int r = row0 + warp_m * 64 + mf * 16 + (lane >> 2);
                int c = n0 + warp_n * 32 + nf * 8 + (lane & 3) * 2;
                if (EPI == 0) {
                    *(float2*)(C + (size_t)r * N + c) =
                        make_float2(acc[mf][nf][0], acc[mf][nf][1]);
                    *(float2*)(C + (size_t)(r + 8) * N + c) =
                        make_float2(acc[mf][nf][2], acc[mf][nf][3]);
                } else {
                    __half2 h0 = __float22half2_rn(make_float2(acc[mf][nf][0], acc[mf][nf][1]));
                    __half2 h1 = __float22half2_rn(make_float2(acc[mf][nf][2], acc[mf][nf][3]));
                    *(u32*)(Ch + (size_t)r * N + c) = *(u32*)&h0;
                    *(u32*)(Ch + (size_t)(r + 8) * N + c) = *(u32*)&h1;
                }
            }
    }
}

extern "C" void kernel_launch(void* const* d_in, const int* in_sizes, int n_in,
                              void* d_out, int out_size)
{
    const float* hiddens = (const float*)d_in[0];
    const int*   bsz     = (const int*)d_in[1];
    const float* w1      = (const float*)d_in[2];
    const float* w2      = (const float*)d_in[3];
    float*       out     = (float*)d_out;

    __half *xh, *w1h, *w2h, *uph;
    cudaGetSymbolAddress((void**)&xh, g_xh);
    cudaGetSymbolAddress((void**)&w1h, g_w1h);
    cudaGetSymbolAddress((void**)&w2h, g_w2h);
    cudaGetSymbolAddress((void**)&uph, g_uph);

    cudaFuncSetAttribute(gemm_moe<1024, 4096, 1>, cudaFuncAttributeMaxDynamicSharedMemorySize, SMEM_BYTES);
    cudaFuncSetAttribute(gemm_moe<4096, 1024, 0>, cudaFuncAttributeMaxDynamicSharedMemorySize, SMEM_BYTES);

    {
        int n4 = (TT * HH) / 4;
        cvt_hi_k<<<(n4 + 255) / 256, 256>>>((const float4*)hiddens, (uint2*)xh, n4);
    }
    {
        int n4 = (NE * HH * II) / 4;
        cvt_hi_k<<<(n4 + 255) / 256, 256>>>((const float4*)w1, (uint2*)w1h, n4);
        cvt_hi_k<<<(n4 + 255) / 256, 256>>>((const float4*)w2, (uint2*)w2h, n4);
    }

    // up = hiddens @ w1[e] : K=1024, N=4096 ; tiles = 64*64 = 4096 ; 3 CTAs/SM
    gemm_moe<1024, 4096, 1><<<NSM * 3, 128, SMEM_BYTES>>>(
        xh, w1h, bsz, nullptr, uph, (II / 64) * (TT / 128));
    // down = up @ w2[e] : K=4096, N=1024 ; tiles = 16*64 = 1024 ; 2 CTAs/SM
    gemm_moe<4096, 1024, 0><<<NSM * 2, 128, SMEM_BYTES>>>(
        uph, w2h, bsz, out, nullptr, (HH / 64) * (TT / 128));
}

// round 16
// speedup vs baseline: 1.1221x; 1.1221x over previous
#include <cuda_runtime.h>
#include <cuda_fp16.h>

#define NE 8
#define TT 8192
#define HH 1024
#define II 4096

typedef unsigned int u32;

// ---- pure fp16 operand planes ----
__device__ __half g_xh[(size_t)TT * HH];
__device__ __half g_w1h[(size_t)NE * HH * II];
__device__ __half g_w2h[(size_t)NE * II * HH];
__device__ __half g_uph[(size_t)TT * II];

// ---- smem stage (halves): A [128][40], B [32][136], BK = 32 ----
#define A_ROW 40
#define B_ROW 136
#define OFF_BH  (128 * A_ROW)                  // 5120
#define STAGE_H (OFF_BH + 32 * B_ROW)          // 9472 halves
#define STAGE_B (STAGE_H * 2)                  // 18944 bytes
#define NSTAGE  3
#define SMEM_BYTES (NSTAGE * STAGE_B)          // 56832 (x2 CTAs = 114KB/SM)

static __device__ __forceinline__ u32 smem_u32(const void* p) {
    u32 a;
    asm("{ .reg .u64 t; cvta.to.shared.u64 t, %1; cvt.u32.u64 %0, t; }" : "=r"(a) : "l"(p));
    return a;
}

#define CP16(dst, src) \
    asm volatile("cp.async.cg.shared.global [%0], [%1], 16;" :: "r"(dst), "l"(src))
#define CP_COMMIT() asm volatile("cp.async.commit_group;" ::: "memory")
#define CP_WAIT1()  asm volatile("cp.async.wait_group 1;" ::: "memory")

#define LDSM4(r, addr)                                                        \
    asm volatile("ldmatrix.sync.aligned.m8n8.x4.shared.b16 {%0,%1,%2,%3}, [%4];" \
                 : "=r"((r)[0]), "=r"((r)[1]), "=r"((r)[2]), "=r"((r)[3])     \
                 : "r"(addr))

#define LDSM4T(r, addr)                                                       \
    asm volatile("ldmatrix.sync.aligned.m8n8.x4.trans.shared.b16 {%0,%1,%2,%3}, [%4];" \
                 : "=r"((r)[0]), "=r"((r)[1]), "=r"((r)[2]), "=r"((r)[3])     \
                 : "r"(addr))

#define MMA16816(d, a, b0, b1)                                                \
    asm volatile("mma.sync.aligned.m16n8k16.row.col.f32.f16.f16.f32 "         \
                 "{%0,%1,%2,%3},{%4,%5,%6,%7},{%8,%9},{%0,%1,%2,%3};"         \
                 : "+f"((d)[0]), "+f"((d)[1]), "+f"((d)[2]), "+f"((d)[3])     \
                 : "r"((a)[0]), "r"((a)[1]), "r"((a)[2]), "r"((a)[3]),        \
                   "r"(b0), "r"(b1))

// fp32 -> fp16 plane
__global__ __launch_bounds__(256)
void cvt_hi_k(const float4* __restrict__ src, uint2* __restrict__ h, int n4)
{
    int i = blockIdx.x * 256 + threadIdx.x;
    if (i < n4) {
        float4 v = src[i];
        __half2 h0 = __float22half2_rn(make_float2(v.x, v.y));
        __half2 h1 = __float22half2_rn(make_float2(v.z, v.w));
        h[i] = make_uint2(*(u32*)&h0, *(u32*)&h1);
    }
}

// C[row0:+128, n0:+128] = A[rows,:K] @ W[e,:K,n0:+128], pure fp16 operands.
// 256 threads, 8 warps (2m x 4n), warp tile 64x32.
// EPI=0: fp32 C.  EPI=1: fp16 Ch.
template <int K, int N, int EPI>
__global__ __launch_bounds__(256, 2)
void gemm_moe(const __half* __restrict__ Ah, const __half* __restrict__ Wh,
              const int* __restrict__ bsz, float* __restrict__ C,
              __half* __restrict__ Ch)
{
    extern __shared__ __half sm[];
    const u32 sbase = smem_u32(sm);
    const int tid = threadIdx.x;
    const int lane = tid & 31;
    const int wid = tid >> 5;
    const int warp_m = wid & 1;    // 2 warps along m (64 rows each)
    const int warp_n = wid >> 1;   // 4 warps along n (32 cols each)
    const int row0 = blockIdx.y * 128;
    const int n0 = blockIdx.x * 128;

    int cum = 0, e = 0;
#pragma unroll
    for (int i = 0; i < NE; i++) { if (row0 >= cum) e = i; cum += bsz[i]; }
    const size_t woff = (size_t)e * (size_t)K * (size_t)N;

    // ---- cp.async mapping (256 threads): A 2 chunks, B 2 chunks ----
    const int ar = tid >> 2, ac = tid & 3;   // A: rows ar, ar+64 ; chunk ac of 4
    const int bk = tid >> 4, bc = tid & 15;  // B: rows bk, bk+16 ; chunk bc of 16
    const __half* pAh = Ah + (size_t)(row0 + ar) * K + ac * 8;
    const __half* pBh = Wh + woff + (size_t)bk * N + n0 + bc * 8;
    const u32 dA = sbase + (u32)((ar * A_ROW + ac * 8) * 2);
    const u32 dB = sbase + (u32)(OFF_BH * 2 + (bk * B_ROW + bc * 8) * 2);

    // ---- ldmatrix lane bases ----
    const int a_r = lane & 15, a_c = (lane >> 4) * 8;
    const u32 aoff = sbase + (u32)(((warp_m * 64 + a_r) * A_ROW + a_c) * 2);
    const int b_k = (lane & 7) + 8 * ((lane >> 3) & 1);
    const int b_n = 8 * (lane >> 4);
    const u32 boff = sbase + (u32)((OFF_BH + b_k * B_ROW + warp_n * 32 + b_n) * 2);

    float acc[4][4][4];
#pragma unroll
    for (int mf = 0; mf < 4; mf++)
#pragma unroll
        for (int nf = 0; nf < 4; nf++)
#pragma unroll
            for (int v = 0; v < 4; v++) acc[mf][nf][v] = 0.0f;

    // single-buffered fragments (double-buffering measured neutral in R12)
    u32 fA[16], fB[8];

    const int NS = K >> 5;

#define LOAD_STAGE(stoff)                                                     \
    do {                                                                      \
        const u32 _a = dA + (stoff);                                          \
        const u32 _b = dB + (stoff);                                          \
        CP16(_a,                       pAh);                                  \
        CP16(_a + 64 * A_ROW * 2,      pAh + (size_t)64 * K);                 \
        CP16(_b,                       pBh);                                  \
        CP16(_b + 16 * B_ROW * 2,      pBh + (size_t)16 * N);                 \
        pAh += 32;                                                            \
        pBh += (size_t)32 * N;                                                \
    } while (0)

#define LDSM_FRAGS(stoff, ki)                                                 \
    do {                                                                      \
        const u32 _ka = aoff + (stoff) + (ki) * 32;                           \
        const u32 _kb = boff + (stoff) + (ki) * (16 * B_ROW * 2);             \
        LDSM4(&fA[0],  _ka);                                                  \
        LDSM4(&fA[4],  _ka + 16 * A_ROW * 2);                                 \
        LDSM4(&fA[8],  _ka + 32 * A_ROW * 2);                                 \
        LDSM4(&fA[12], _ka + 48 * A_ROW * 2);                                 \
        LDSM4T(&fB[0], _kb);                                                  \
        LDSM4T(&fB[4], _kb + 16 * 2);                                         \
    } while (0)

#define BURST()                                                               \
    do {                                                                      \
        _Pragma("unroll")                                                     \
        for (int mf = 0; mf < 4; mf++)                                        \
            _Pragma("unroll")                                                 \
            for (int nf = 0; nf < 4; nf++)                                    \
                MMA16816(acc[mf][nf], &fA[mf * 4], fB[nf * 2],                \
                         fB[nf * 2 + 1]);                                     \
    } while (0)

    LOAD_STAGE(0);         CP_COMMIT();
    LOAD_STAGE(STAGE_B);   CP_COMMIT();

    int sidx = 0;
    for (int s = 0; s < NS; s++) {
        CP_WAIT1();
        __syncthreads();

        if (s + 2 < NS) {
            int pidx = sidx + 2; if (pidx >= 3) pidx -= 3;
            LOAD_STAGE((u32)(pidx * STAGE_B));
        }
        CP_COMMIT();

        const u32 stb = (u32)(sidx * STAGE_B);
        sidx++; if (sidx >= 3) sidx -= 3;

        LDSM_FRAGS(stb, 0);
        BURST();
        LDSM_FRAGS(stb, 1);
        BURST();
    }
#undef LOAD_STAGE
#undef LDSM_FRAGS
#undef BURST

    // ---- epilogue ----
#pragma unroll
    for (int mf = 0; mf < 4; mf++)
#pragma unroll
        for (int nf = 0; nf < 4; nf++) {
            int r = row0 + warp_m * 64 + mf * 16 + (lane >> 2);
            int c = n0 + warp_n * 32 + nf * 8 + (lane & 3) * 2;
            if (EPI == 0) {
                *(float2*)(C + (size_t)r * N + c) =
                    make_float2(acc[mf][nf][0], acc[mf][nf][1]);
                *(float2*)(C + (size_t)(r + 8) * N + c) =
                    make_float2(acc[mf][nf][2], acc[mf][nf][3]);
            } else {
                __half2 h0 = __float22half2_rn(make_float2(acc[mf][nf][0], acc[mf][nf][1]));
                __half2 h1 = __float22half2_rn(make_float2(acc[mf][nf][2], acc[mf][nf][3]));
                *(u32*)(Ch + (size_t)r * N + c) = *(u32*)&h0;
                *(u32*)(Ch + (size_t)(r + 8) * N + c) = *(u32*)&h1;
            }
        }
}

extern "C" void kernel_launch(void* const* d_in, const int* in_sizes, int n_in,
                              void* d_out, int out_size)
{
    const float* hiddens = (const float*)d_in[0];
    const int*   bsz     = (const int*)d_in[1];
    const float* w1      = (const float*)d_in[2];
    const float* w2      = (const float*)d_in[3];
    float*       out     = (float*)d_out;

    __half *xh, *w1h, *w2h, *uph;
    cudaGetSymbolAddress((void**)&xh, g_xh);
    cudaGetSymbolAddress((void**)&w1h, g_w1h);
    cudaGetSymbolAddress((void**)&w2h, g_w2h);
    cudaGetSymbolAddress((void**)&uph, g_uph);

    cudaFuncSetAttribute(gemm_moe<1024, 4096, 1>, cudaFuncAttributeMaxDynamicSharedMemorySize, SMEM_BYTES);
    cudaFuncSetAttribute(gemm_moe<4096, 1024, 0>, cudaFuncAttributeMaxDynamicSharedMemorySize, SMEM_BYTES);

    {
        int n4 = (TT * HH) / 4;
        cvt_hi_k<<<(n4 + 255) / 256, 256>>>((const float4*)hiddens, (uint2*)xh, n4);
    }
    {
        int n4 = (NE * HH * II) / 4;
        cvt_hi_k<<<(n4 + 255) / 256, 256>>>((const float4*)w1, (uint2*)w1h, n4);
        cvt_hi_k<<<(n4 + 255) / 256, 256>>>((const float4*)w2, (uint2*)w2h, n4);
    }

    // up = hiddens @ w1[e] : K=1024, N=4096 ; fp16 output ; grid 32x64
    gemm_moe<1024, 4096, 1><<<dim3(II / 128, TT / 128), 256, SMEM_BYTES>>>(
        xh, w1h, bsz, nullptr, uph);
    // down = up @ w2[e] : K=4096, N=1024 ; fp32 output ; grid 8x64
    gemm_moe<4096, 1024, 0><<<dim3(HH / 128, TT / 128), 256, SMEM_BYTES>>>(
        uph, w2h, bsz, out, nullptr);
}

// round 17
// speedup vs baseline: 1.1259x; 1.0034x over previous
#include <cuda_runtime.h>
#include <cuda_fp16.h>

#define NE 8
#define TT 8192
#define HH 1024
#define II 4096

typedef unsigned int u32;

// ---- pure fp16 operand planes ----
__device__ __half g_xh[(size_t)TT * HH];
__device__ __half g_w1h[(size_t)NE * HH * II];
__device__ __half g_w2h[(size_t)NE * II * HH];
__device__ __half g_uph[(size_t)TT * II];

// ---- smem stage (halves): A [128][40], B [32][136], BK = 32 ----
#define A_ROW 40
#define B_ROW 136
#define OFF_BH  (128 * A_ROW)                  // 5120
#define STAGE_H (OFF_BH + 32 * B_ROW)          // 9472 halves
#define STAGE_B (STAGE_H * 2)                  // 18944 bytes
#define NSTAGE  3
#define SMEM_BYTES (NSTAGE * STAGE_B)          // 56832 (x2 CTAs = 114KB/SM)

static __device__ __forceinline__ u32 smem_u32(const void* p) {
    u32 a;
    asm("{ .reg .u64 t; cvta.to.shared.u64 t, %1; cvt.u32.u64 %0, t; }" : "=r"(a) : "l"(p));
    return a;
}

#define CP16(dst, src) \
    asm volatile("cp.async.cg.shared.global [%0], [%1], 16;" :: "r"(dst), "l"(src))
#define CP_COMMIT() asm volatile("cp.async.commit_group;" ::: "memory")
#define CP_WAIT1()  asm volatile("cp.async.wait_group 1;" ::: "memory")

#define LDSM4(r, addr)                                                        \
    asm volatile("ldmatrix.sync.aligned.m8n8.x4.shared.b16 {%0,%1,%2,%3}, [%4];" \
                 : "=r"((r)[0]), "=r"((r)[1]), "=r"((r)[2]), "=r"((r)[3])     \
                 : "r"(addr))

#define LDSM4T(r, addr)                                                       \
    asm volatile("ldmatrix.sync.aligned.m8n8.x4.trans.shared.b16 {%0,%1,%2,%3}, [%4];" \
                 : "=r"((r)[0]), "=r"((r)[1]), "=r"((r)[2]), "=r"((r)[3])     \
                 : "r"(addr))

#define MMA16816(d, a, b0, b1)                                                \
    asm volatile("mma.sync.aligned.m16n8k16.row.col.f32.f16.f16.f32 "         \
                 "{%0,%1,%2,%3},{%4,%5,%6,%7},{%8,%9},{%0,%1,%2,%3};"         \
                 : "+f"((d)[0]), "+f"((d)[1]), "+f"((d)[2]), "+f"((d)[3])     \
                 : "r"((a)[0]), "r"((a)[1]), "r"((a)[2]), "r"((a)[3]),        \
                   "r"(b0), "r"(b1))

// fp32 -> fp16 plane
__global__ __launch_bounds__(256)
void cvt_hi_k(const float4* __restrict__ src, uint2* __restrict__ h, int n4)
{
    int i = blockIdx.x * 256 + threadIdx.x;
    if (i < n4) {
        float4 v = src[i];
        __half2 h0 = __float22half2_rn(make_float2(v.x, v.y));
        __half2 h1 = __float22half2_rn(make_float2(v.z, v.w));
        h[i] = make_uint2(*(u32*)&h0, *(u32*)&h1);
    }
}

// C[row0:+128, n0:+128] = A[rows,:K] @ W[e,:K,n0:+128], pure fp16 operands.
// 256 threads, 8 warps (2m x 4n), warp tile 64x32.
// EPI=0: fp32 C.  EPI=1: fp16 Ch.
template <int K, int N, int EPI>
__global__ __launch_bounds__(256, 2)
void gemm_moe(const __half* __restrict__ Ah, const __half* __restrict__ Wh,
              const int* __restrict__ bsz, float* __restrict__ C,
              __half* __restrict__ Ch)
{
    extern __shared__ __half sm[];
    const u32 sbase = smem_u32(sm);
    const int tid = threadIdx.x;
    const int lane = tid & 31;
    const int wid = tid >> 5;
    const int warp_m = wid & 1;    // 2 warps along m (64 rows each)
    const int warp_n = wid >> 1;   // 4 warps along n (32 cols each)
    const int row0 = blockIdx.y * 128;
    const int n0 = blockIdx.x * 128;

    int cum = 0, e = 0;
#pragma unroll
    for (int i = 0; i < NE; i++) { if (row0 >= cum) e = i; cum += bsz[i]; }
    const size_t woff = (size_t)e * (size_t)K * (size_t)N;

    // ---- cp.async mapping (256 threads): A 2 chunks, B 2 chunks ----
    const int ar = tid >> 2, ac = tid & 3;   // A: rows ar, ar+64 ; chunk ac of 4
    const int bk = tid >> 4, bc = tid & 15;  // B: rows bk, bk+16 ; chunk bc of 16
    const __half* pAh = Ah + (size_t)(row0 + ar) * K + ac * 8;
    const __half* pBh = Wh + woff + (size_t)bk * N + n0 + bc * 8;
    const u32 dA = sbase + (u32)((ar * A_ROW + ac * 8) * 2);
    const u32 dB = sbase + (u32)(OFF_BH * 2 + (bk * B_ROW + bc * 8) * 2);

    // ---- ldmatrix lane bases ----
    const int a_r = lane & 15, a_c = (lane >> 4) * 8;
    const u32 aoff = sbase + (u32)(((warp_m * 64 + a_r) * A_ROW + a_c) * 2);
    const int b_k = (lane & 7) + 8 * ((lane >> 3) & 1);
    const int b_n = 8 * (lane >> 4);
    const u32 boff = sbase + (u32)((OFF_BH + b_k * B_ROW + warp_n * 32 + b_n) * 2);

    float acc[4][4][4];
#pragma unroll
    for (int mf = 0; mf < 4; mf++)
#pragma unroll
        for (int nf = 0; nf < 4; nf++)
#pragma unroll
            for (int v = 0; v < 4; v++) acc[mf][nf][v] = 0.0f;

    u32 fA[16], fB[8];

    const int NS = K >> 5;

#define LOAD_STAGE(stoff)                                                     \
    do {                                                                      \
        const u32 _a = dA + (stoff);                                          \
        const u32 _b = dB + (stoff);                                          \
        CP16(_a,                       pAh);                                  \
        CP16(_a + 64 * A_ROW * 2,      pAh + (size_t)64 * K);                 \
        CP16(_b,                       pBh);                                  \
        CP16(_b + 16 * B_ROW * 2,      pBh + (size_t)16 * N);                 \
        pAh += 32;                                                            \
        pBh += (size_t)32 * N;                                                \
    } while (0)

#define LDSM_FRAGS(stoff, ki)                                                 \
    do {                                                                      \
        const u32 _ka = aoff + (stoff) + (ki) * 32;                           \
        const u32 _kb = boff + (stoff) + (ki) * (16 * B_ROW * 2);             \
        LDSM4(&fA[0],  _ka);                                                  \
        LDSM4(&fA[4],  _ka + 16 * A_ROW * 2);                                 \
        LDSM4(&fA[8],  _ka + 32 * A_ROW * 2);                                 \
        LDSM4(&fA[12], _ka + 48 * A_ROW * 2);                                 \
        LDSM4T(&fB[0], _kb);                                                  \
        LDSM4T(&fB[4], _kb + 16 * 2);                                         \
    } while (0)

#define BURST()                                                               \
    do {                                                                      \
        _Pragma("unroll")                                                     \
        for (int mf = 0; mf < 4; mf++)                                        \
            _Pragma("unroll")                                                 \
            for (int nf = 0; nf < 4; nf++)                                    \
                MMA16816(acc[mf][nf], &fA[mf * 4], fB[nf * 2],                \
                         fB[nf * 2 + 1]);                                     \
    } while (0)

    LOAD_STAGE(0);         CP_COMMIT();
    LOAD_STAGE(STAGE_B);   CP_COMMIT();

    int sidx = 0;
    for (int s = 0; s < NS; s++) {
        CP_WAIT1();
        __syncthreads();

        if (s + 2 < NS) {
            int pidx = sidx + 2; if (pidx >= 3) pidx -= 3;
            LOAD_STAGE((u32)(pidx * STAGE_B));
        }
        CP_COMMIT();

        const u32 stb = (u32)(sidx * STAGE_B);
        sidx++; if (sidx >= 3) sidx -= 3;

        LDSM_FRAGS(stb, 0);
        BURST();
        LDSM_FRAGS(stb, 1);
        BURST();
    }
#undef LOAD_STAGE
#undef LDSM_FRAGS
#undef BURST

    // ---- epilogue ----
#pragma unroll
    for (int mf = 0; mf < 4; mf++)
#pragma unroll
        for (int nf = 0; nf < 4; nf++) {
            int r = row0 + warp_m * 64 + mf * 16 + (lane >> 2);
            int c = n0 + warp_n * 32 + nf * 8 + (lane & 3) * 2;
            if (EPI == 0) {
                *(float2*)(C + (size_t)r * N + c) =
                    make_float2(acc[mf][nf][0], acc[mf][nf][1]);
                *(float2*)(C + (size_t)(r + 8) * N + c) =
                    make_float2(acc[mf][nf][2], acc[mf][nf][3]);
            } else {
                __half2 h0 = __float22half2_rn(make_float2(acc[mf][nf][0], acc[mf][nf][1]));
                __half2 h1 = __float22half2_rn(make_float2(acc[mf][nf][2], acc[mf][nf][3]));
                *(u32*)(Ch + (size_t)r * N + c) = *(u32*)&h0;
                *(u32*)(Ch + (size_t)(r + 8) * N + c) = *(u32*)&h1;
            }
        }
}

extern "C" void kernel_launch(void* const* d_in, const int* in_sizes, int n_in,
                              void* d_out, int out_size)
{
    const float* hiddens = (const float*)d_in[0];
    const int*   bsz     = (const int*)d_in[1];
    const float* w1      = (const float*)d_in[2];
    const float* w2      = (const float*)d_in[3];
    float*       out     = (float*)d_out;

    __half *xh, *w1h, *w2h, *uph;
    cudaGetSymbolAddress((void**)&xh, g_xh);
    cudaGetSymbolAddress((void**)&w1h, g_w1h);
    cudaGetSymbolAddress((void**)&w2h, g_w2h);
    cudaGetSymbolAddress((void**)&uph, g_uph);

    cudaFuncSetAttribute(gemm_moe<1024, 4096, 1>, cudaFuncAttributeMaxDynamicSharedMemorySize, SMEM_BYTES);
    cudaFuncSetAttribute(gemm_moe<4096, 1024, 0>, cudaFuncAttributeMaxDynamicSharedMemorySize, SMEM_BYTES);

    // Fork a side branch in the captured graph: cvt_w2 runs concurrently with
    // {cvt_x, cvt_w1, GEMM1} (no data dependency; GEMM1 leaves DRAM ~92% idle).
    cudaStream_t s2;
    cudaEvent_t eFork, eW2;
    bool forked = (cudaStreamCreateWithFlags(&s2, cudaStreamNonBlocking) == cudaSuccess) &&
                  (cudaEventCreateWithFlags(&eFork, cudaEventDisableTiming) == cudaSuccess) &&
                  (cudaEventCreateWithFlags(&eW2, cudaEventDisableTiming) == cudaSuccess);

    {
        int n4w = (NE * HH * II) / 4;
        if (forked && cudaEventRecord(eFork, 0) == cudaSuccess &&
            cudaStreamWaitEvent(s2, eFork, 0) == cudaSuccess) {
            cvt_hi_k<<<(n4w + 255) / 256, 256, 0, s2>>>((const float4*)w2, (uint2*)w2h, n4w);
            cudaEventRecord(eW2, s2);
        } else {
            forked = false;
            cvt_hi_k<<<(n4w + 255) / 256, 256>>>((const float4*)w2, (uint2*)w2h, n4w);
        }

        int n4x = (TT * HH) / 4;
        cvt_hi_k<<<(n4x + 255) / 256, 256>>>((const float4*)hiddens, (uint2*)xh, n4x);
        cvt_hi_k<<<(n4w + 255) / 256, 256>>>((const float4*)w1, (uint2*)w1h, n4w);
    }

    // up = hiddens @ w1[e] : K=1024, N=4096 ; fp16 output ; grid 32x64
    gemm_moe<1024, 4096, 1><<<dim3(II / 128, TT / 128), 256, SMEM_BYTES>>>(
        xh, w1h, bsz, nullptr, uph);

    // join: GEMM2 needs w2h
    if (forked) cudaStreamWaitEvent(0, eW2, 0);

    // down = up @ w2[e] : K=4096, N=1024 ; fp32 output ; grid 8x64
    gemm_moe<4096, 1024, 0><<<dim3(HH / 128, TT / 128), 256, SMEM_BYTES>>>(
        uph, w2h, bsz, out, nullptr);

    if (forked) {
        cudaStreamDestroy(s2);
        cudaEventDestroy(eFork);
        cudaEventDestroy(eW2);
    }
}